// round 10
// baseline (speedup 1.0000x reference)
#include <cuda_runtime.h>
#include <math.h>

#define NTHR 512
#define TRIPS 8
#define NBLK 4096
typedef unsigned long long ull;

// smem float offsets
#define WBUF0  0        // [ws 2500 | wg 2500 | wv 2500], layer parity 0
#define WBUF1  7500     // parity 1
#define HIDS   0        // [6][64][8] alias in WBUF0, pre-loop only
#define WALLS  15000    // [6][8][104] edge-0 radial weights
#define GEOS   19992    // [8][40]
#define TSTATE 20312    // [8][800]
#define OF_H   0        // float4[50]: {h4,h3,h5,0}
#define OF_VC  200      // [50][8]: {v4x,v4y,v3x,v3y},{v3z,v5x,v5y,v5z}  (v4z==0 always)
#define OF_G   600      // float4[50]: {g4,g3,g5,s4'}
#define TSF    800
#define SMEM_FLOATS (TSTATE + TRIPS * TSF)   // 26712
#define SMEM_BYTES  (SMEM_FLOATS * 4)        // 106848

__device__ float g_s1[6][50];
__device__ float g_w1[6][256];

__device__ __forceinline__ float sigm_f(float x) { return 1.0f / (1.0f + __expf(-x)); }
__device__ __forceinline__ float silu_f(float x) { return x / (1.0f + __expf(-x)); }
__device__ __forceinline__ ull fma2(ull a, ull b, ull c) {
    ull d; asm("fma.rn.f32x2 %0, %1, %2, %3;" : "=l"(d) : "l"(a), "l"(b), "l"(c)); return d;
}
__device__ __forceinline__ ull pack2(float lo, float hi) {
    ull d; asm("mov.b64 %0, {%1, %2};" : "=l"(d) : "f"(lo), "f"(hi)); return d;
}
__device__ __forceinline__ void unpack2(ull v, float& lo, float& hi) {
    asm("mov.b64 {%0, %1}, %2;" : "=f"(lo), "=f"(hi) : "l"(v));
}
__device__ __forceinline__ float halfsel(ull v, int hi) {
    float a, b; unpack2(v, a, b); return hi ? b : a;
}
__device__ __forceinline__ void pbar(int id) {   // A2-B2 pair barrier, 64 threads
    asm volatile("bar.sync %0, %1;" :: "r"(id), "r"(64) : "memory");
}

__global__ void setup_kernel(const float* __restrict__ We, const float* __restrict__ Wr1g,
                             const float* __restrict__ br1g, const float* __restrict__ Wr2g,
                             const float* __restrict__ Wsg) {
    __shared__ float hid[64];
    __shared__ float s[50];
    __shared__ float sn[50];
    int k = threadIdx.x;
    const float fc = 0.5f * (cosf(3.14159265358979f * (0.05f / 0.06f)) + 1.0f);
    if (k < 50) s[k] = We[k] + We[50 + k];
    for (int l = 0; l < 6; l++) {
        __syncthreads();
        if (k < 64) {
            float acc = br1g[l * 64 + k];
            #pragma unroll
            for (int ib = 0; ib < 10; ib++) {
                float z = 7.5f - (float)ib;
                acc += __expf(-z * z) * fc * Wr1g[l * 768 + ib * 64 + k];
            }
            acc += Wr1g[l * 768 + 11 * 64 + k];
            hid[k] = silu_f(acc);
        }
        if (k < 50) {
            g_s1[l][k] = s[k];
            float acc = 0.f;
            for (int c = 0; c < 50; c++) acc += s[c] * Wsg[l * 2500 + c * 50 + k];
            sn[k] = silu_f(acc);
        }
        __syncthreads();
        if (k < 50) s[k] = sn[k];
        if (k < 250) {
            float acc = 0.f;
            for (int j = 0; j < 64; j++) acc += hid[j] * Wr2g[l * 16000 + j * 250 + k];
            g_w1[l][k] = acc * fc;
        }
    }
}

__global__ void __launch_bounds__(NTHR, 2)
e3nn_kernel(const float* __restrict__ y, const float* __restrict__ Wemb,
            const float* __restrict__ Wr1g, const float* __restrict__ br1g,
            const float* __restrict__ Wr2g, const float* __restrict__ Wsg,
            const float* __restrict__ Wvg, const float* __restrict__ Wgg,
            const float* __restrict__ Woutg, float* __restrict__ outp)
{
    extern __shared__ float sm[];
    const int tid  = threadIdx.x;
    const int trip = tid >> 6;          // pre-loop / init / epilogue mapping
    const int k    = tid & 63;
    const int wid  = tid >> 5;
    const int lane = tid & 31;
    float* g  = sm + GEOS + trip * 40;
    float* st = sm + TSTATE + trip * TSF;
    const int t = blockIdx.x * TRIPS + trip;
    const int b = t >> 9;
    const int i = t & 511;

    // ---- geometry ----
    if (k < 2) {
        const float* yy = y + (size_t)(b * 514 + i + k) * 6;
        float a = yy[2];
        float* bs = g + 28 + k * 4;
        bs[0] = yy[0]; bs[1] = yy[1];
        bs[2] = -0.05f * sinf(a); bs[3] = 0.05f * cosf(a);
    }
    __syncthreads();
    if (k == 0) {
        float vx = g[28] - g[32], vy = g[29] - g[33];   // edge 1->4
        float r = sqrtf(vx * vx + vy * vy);
        float inv = 1.0f / (r + 1e-12f);
        g[0] = vx * inv; g[1] = vy * inv;
        float ox = g[34], oy = g[35];
        g[2] = -ox * 20.f; g[3] = -oy * 20.f;           // u1 = -off/0.05
        float tt = fminf(r * (1.0f / 0.06f), 1.0f);
        float fc = 0.5f * (cosf(3.14159265358979f * tt) + 1.0f);
        g[16] = fc;
        #pragma unroll
        for (int ib = 0; ib < 10; ib++) {
            float z = r * 150.f - (float)ib;
            g[4 + ib] = __expf(-z * z) * fc;
        }
        g[14] = 1.f; g[15] = 0.f;                       // edge-0 one-hot attr
        g[17] = ox; g[18] = oy;
        float u3[3] = {g[2], g[3], 0.f};
        #pragma unroll
        for (int rr = 0; rr < 3; rr++)
            #pragma unroll
            for (int cc = 0; cc < 3; cc++)
                g[19 + rr * 3 + cc] = u3[rr] * u3[cc] - (rr == cc ? (1.f / 3.f) : 0.f);
    }
    __syncthreads();

    // ---- pre-loop A: edge-0 hidden, all 6 layers, trip-minor (aliased in WBUF0) ----
    {
        const float fcut0 = g[16];
        #pragma unroll
        for (int l = 0; l < 6; l++) {
            float acc = __ldg(br1g + l * 64 + k);
            const float* wr1 = Wr1g + l * 768 + k;
            #pragma unroll
            for (int ii = 0; ii < 12; ii++) acc += g[4 + ii] * __ldg(wr1 + ii * 64);
            sm[HIDS + (l * 64 + k) * 8 + trip] = silu_f(acc) * fcut0;
        }
    }
    __syncthreads();

    // ---- pre-loop B: radial weights, layer-parallel, 8 trips per lane ----
    if (wid < 12) {
        const int l = wid >> 1;
        const int pk = ((wid & 1) << 5) + lane;
        if (pk < 50) {
            const float* wb = Wr2g + (size_t)l * 16000 + 2 * pk;
            const float* hb = sm + HIDS + l * 512;
            ull a0 = 0, a1 = 0, a2 = 0, a3 = 0, a4 = 0, a5 = 0, a6 = 0, a7 = 0;
            #pragma unroll 4
            for (int j = 0; j < 64; j++) {
                ull wv = __ldg((const ull*)(wb + (size_t)j * 250));
                float4 ha = *(const float4*)(hb + j * 8);
                float4 hc = *(const float4*)(hb + j * 8 + 4);
                a0 = fma2(pack2(ha.x, ha.x), wv, a0);
                a1 = fma2(pack2(ha.y, ha.y), wv, a1);
                a2 = fma2(pack2(ha.z, ha.z), wv, a2);
                a3 = fma2(pack2(ha.w, ha.w), wv, a3);
                a4 = fma2(pack2(hc.x, hc.x), wv, a4);
                a5 = fma2(pack2(hc.y, hc.y), wv, a5);
                a6 = fma2(pack2(hc.z, hc.z), wv, a6);
                a7 = fma2(pack2(hc.w, hc.w), wv, a7);
            }
            float* wl = sm + WALLS + l * 832 + 2 * pk;
            *(ull*)(wl + 0 * 104) = a0; *(ull*)(wl + 1 * 104) = a1;
            *(ull*)(wl + 2 * 104) = a2; *(ull*)(wl + 3 * 104) = a3;
            *(ull*)(wl + 4 * 104) = a4; *(ull*)(wl + 5 * 104) = a5;
            *(ull*)(wl + 6 * 104) = a6; *(ull*)(wl + 7 * 104) = a7;
        }
    }
    __syncthreads();

    // ---- stage layer-0 weights into buf0 + init state with layer-0 messages ----
    {
        float4* dst = (float4*)(sm + WBUF0);
        const float4* ws4 = (const float4*)Wsg;
        const float4* wg4 = (const float4*)Wgg;
        const float4* wv4 = (const float4*)Wvg;
        for (int idx = tid; idx < 625; idx += NTHR) {
            dst[idx] = ws4[idx];
            dst[idx + 625] = wg4[idx];
            dst[idx + 1250] = wv4[idx];
        }
    }
    if (k < 50) {
        float e0 = Wemb[k], e1 = Wemb[50 + k], e2 = Wemb[100 + k];
        float s4i = e0 + e1, s3i = e0 + e2;
        const float* wl = sm + WALLS + trip * 104;
        float w0a = wl[k], w0b = wl[50 + k];
        float w1a = __ldg(&g_w1[0][k]), w1b = __ldg(&g_w1[0][50 + k]);
        float s1v = __ldg(&g_s1[0][k]);
        float h4 = s4i + w0a * s1v;
        float base = w1a * s4i;
        float w01 = w0b * s1v;
        float mv4x = w01 * g[0], mv4y = w01 * g[1];
        float a_ = w1b * s4i;
        float v3x = a_ * g[2], v3y = a_ * g[3];
        *(float4*)(st + OF_H + k * 4) = make_float4(h4, s3i + base, s3i + base, 0.f);
        *(float4*)(st + OF_VC + k * 8)     = make_float4(mv4x, mv4y, v3x, v3y);
        *(float4*)(st + OF_VC + k * 8 + 4) = make_float4(0.f, -v3x, -v3y, 0.f);
    }
    __syncthreads();

    // ---- main loop: 4 A2-warps (s/g, 2 trips), 4 B2-warps (v, 2 trips), 8 staging ----
    for (int l = 0; l < 6; l++) {
        const float* wb = sm + (l & 1) * 7500;
        if (wid < 4) {
            // ======== A2: s + gate GEMMs for trips (2w, 2w+1) ========
            const int w = wid;
            float* stA = sm + TSTATE + (2 * w) * TSF;
            float* stB = sm + TSTATE + (2 * w + 1) * TSF;
            if (lane < 25) {
                ull as4A = 0, as3A = 0, as5A = 0, ag4A = 0, ag3A = 0, ag5A = 0;
                ull as4B = 0, as3B = 0, as5B = 0, ag4B = 0, ag3B = 0, ag5B = 0;
                #pragma unroll 2
                for (int c = 0; c < 50; c++) {
                    float wsA = wb[c * 50 + lane],        wsB = wb[c * 50 + lane + 25];
                    float wgA = wb[2500 + c * 50 + lane], wgB = wb[2500 + c * 50 + lane + 25];
                    float4 h0 = *(const float4*)(stA + OF_H + c * 4);
                    float4 h1 = *(const float4*)(stB + OF_H + c * 4);
                    ull h4d = pack2(h0.x, h1.x), h3d = pack2(h0.y, h1.y), h5d = pack2(h0.z, h1.z);
                    ull wsAd = pack2(wsA, wsA), wsBd = pack2(wsB, wsB);
                    ull wgAd = pack2(wgA, wgA), wgBd = pack2(wgB, wgB);
                    as4A = fma2(h4d, wsAd, as4A); as3A = fma2(h3d, wsAd, as3A); as5A = fma2(h5d, wsAd, as5A);
                    ag4A = fma2(h4d, wgAd, ag4A); ag3A = fma2(h3d, wgAd, ag3A); ag5A = fma2(h5d, wgAd, ag5A);
                    as4B = fma2(h4d, wsBd, as4B); as3B = fma2(h3d, wsBd, as3B); as5B = fma2(h5d, wsBd, as5B);
                    ag4B = fma2(h4d, wgBd, ag4B); ag3B = fma2(h3d, wgBd, ag3B); ag5B = fma2(h5d, wgBd, ag5B);
                }
                #pragma unroll
                for (int tt = 0; tt < 2; tt++) {
                    float* stT = tt ? stB : stA;
                    const int tg = 2 * w + tt;
                    const float* wl = sm + WALLS + (l + 1) * 832 + tg * 104;
                    #pragma unroll
                    for (int sl = 0; sl < 2; sl++) {
                        int kx = lane + sl * 25;
                        float s4v = silu_f(halfsel(sl ? as4B : as4A, tt));
                        float s3v = silu_f(halfsel(sl ? as3B : as3A, tt));
                        float s5v = silu_f(halfsel(sl ? as5B : as5A, tt));
                        float g4v = sigm_f(halfsel(sl ? ag4B : ag4A, tt));
                        float g3v = sigm_f(halfsel(sl ? ag3B : ag3A, tt));
                        float g5v = sigm_f(halfsel(sl ? ag5B : ag5A, tt));
                        if (l < 5) {
                            float w0a = wl[kx];
                            float s1v = __ldg(&g_s1[l + 1][kx]);
                            float w1a = __ldg(&g_w1[l + 1][kx]);
                            float h4 = s4v + w0a * s1v;
                            float base = w1a * s4v;
                            *(float4*)(stT + OF_H + kx * 4) = make_float4(h4, s3v + base, s5v + base, 0.f);
                        }
                        *(float4*)(stT + OF_G + kx * 4) = make_float4(g4v, g3v, g5v, s4v);
                    }
                }
            }
            pbar(1 + w);
        } else if (wid < 8) {
            // ======== B2: v GEMM + gating + messages for trips (2w, 2w+1) ========
            const int w = wid - 4;
            float* stA = sm + TSTATE + (2 * w) * TSF;
            float* stB = sm + TSTATE + (2 * w + 1) * TSF;
            ull aA[8], aB[8];
            if (lane < 25) {
                #pragma unroll
                for (int z = 0; z < 8; z++) { aA[z] = 0; aB[z] = 0; }
                const float* wvb = wb + 5000;
                #pragma unroll 2
                for (int c = 0; c < 50; c++) {
                    float wvA = wvb[c * 50 + lane], wvB = wvb[c * 50 + lane + 25];
                    ull wvAd = pack2(wvA, wvA), wvBd = pack2(wvB, wvB);
                    float4 p0 = *(const float4*)(stA + OF_VC + c * 8);
                    float4 q0 = *(const float4*)(stA + OF_VC + c * 8 + 4);
                    float4 p1 = *(const float4*)(stB + OF_VC + c * 8);
                    float4 q1 = *(const float4*)(stB + OF_VC + c * 8 + 4);
                    ull r0 = pack2(p0.x, p1.x), r1 = pack2(p0.y, p1.y);
                    ull r2 = pack2(p0.z, p1.z), r3 = pack2(p0.w, p1.w);
                    ull r4 = pack2(q0.x, q1.x), r5 = pack2(q0.y, q1.y);
                    ull r6 = pack2(q0.z, q1.z), r7 = pack2(q0.w, q1.w);
                    aA[0] = fma2(r0, wvAd, aA[0]); aA[1] = fma2(r1, wvAd, aA[1]);
                    aA[2] = fma2(r2, wvAd, aA[2]); aA[3] = fma2(r3, wvAd, aA[3]);
                    aA[4] = fma2(r4, wvAd, aA[4]); aA[5] = fma2(r5, wvAd, aA[5]);
                    aA[6] = fma2(r6, wvAd, aA[6]); aA[7] = fma2(r7, wvAd, aA[7]);
                    aB[0] = fma2(r0, wvBd, aB[0]); aB[1] = fma2(r1, wvBd, aB[1]);
                    aB[2] = fma2(r2, wvBd, aB[2]); aB[3] = fma2(r3, wvBd, aB[3]);
                    aB[4] = fma2(r4, wvBd, aB[4]); aB[5] = fma2(r5, wvBd, aB[5]);
                    aB[6] = fma2(r6, wvBd, aB[6]); aB[7] = fma2(r7, wvBd, aB[7]);
                }
            }
            pbar(1 + w);
            if (lane < 25) {
                #pragma unroll
                for (int tt = 0; tt < 2; tt++) {
                    float* stT = tt ? stB : stA;
                    const int tg = 2 * w + tt;
                    float* mgT = sm + GEOS + tg * 40;
                    float u0x = mgT[0], u0y = mgT[1], u1x = mgT[2], u1y = mgT[3];
                    float Y0 = mgT[19], Y1 = mgT[20], Y2v = mgT[21];
                    float Y3 = mgT[22], Y4 = mgT[23], Y5 = mgT[24];
                    const float* wl = sm + WALLS + (l + 1) * 832 + tg * 104;
                    #pragma unroll
                    for (int sl = 0; sl < 2; sl++) {
                        int kx = lane + sl * 25;
                        const ull* ac = sl ? aB : aA;
                        float4 gg = *(const float4*)(stT + OF_G + kx * 4);
                        float v4x = halfsel(ac[0], tt) * gg.x;
                        float v4y = halfsel(ac[1], tt) * gg.x;
                        float v3x = halfsel(ac[2], tt) * gg.y;
                        float v3y = halfsel(ac[3], tt) * gg.y;
                        float v3z = halfsel(ac[4], tt) * gg.y;
                        float v5x = halfsel(ac[5], tt) * gg.z;
                        float v5y = halfsel(ac[6], tt) * gg.z;
                        float v5z = halfsel(ac[7], tt) * gg.z;
                        if (l < 5) {
                            float w0b = wl[50 + kx];
                            float s1v = __ldg(&g_s1[l + 1][kx]);
                            const float* w1p = g_w1[l + 1];
                            float w1b = __ldg(w1p + 50 + kx),  w1c = __ldg(w1p + 100 + kx);
                            float w1d = __ldg(w1p + 150 + kx), w1e = __ldg(w1p + 200 + kx);
                            float w01 = w0b * s1v;
                            float mv4x = w01 * u0x, mv4y = w01 * u0y;
                            float a_ = w1b * gg.w;
                            float dot = v4x * u1x + v4y * u1y;
                            float wd = w1c * dot;
                            float crz = v4x * u1y - v4y * u1x;
                            float yx = v4x * Y0 + v4y * Y3;
                            float yy2 = v4x * Y1 + v4y * Y4;
                            float yz = v4x * Y2v + v4y * Y5;
                            float axu = a_ * u1x, ayu = a_ * u1y;
                            float bz = w1d * crz;
                            float cx2 = w1e * yx, cy2 = w1e * yy2, cz2 = w1e * yz;
                            float4 hh = *(const float4*)(stT + OF_H + kx * 4);
                            hh.y += wd; hh.z -= wd;
                            *(float4*)(stT + OF_H + kx * 4) = hh;
                            *(float4*)(stT + OF_VC + kx * 8) =
                                make_float4(v4x + mv4x, v4y + mv4y, v3x + axu + cx2, v3y + ayu + cy2);
                            *(float4*)(stT + OF_VC + kx * 8 + 4) =
                                make_float4(v3z + bz + cz2, v5x - axu + cx2, v5y - ayu + cy2, v5z - bz + cz2);
                        } else {
                            *(float4*)(stT + OF_VC + kx * 8)     = make_float4(v4x, v4y, v3x, v3y);
                            *(float4*)(stT + OF_VC + kx * 8 + 4) = make_float4(v3z, v5x, v5y, v5z);
                        }
                    }
                }
            }
        } else {
            // ======== staging: layer l+1 weights into the other buffer ========
            if (l < 5) {
                float4* dst = (float4*)(sm + ((l + 1) & 1) * 7500);
                const float4* ws4 = (const float4*)(Wsg + (size_t)(l + 1) * 2500);
                const float4* wg4 = (const float4*)(Wgg + (size_t)(l + 1) * 2500);
                const float4* wv4 = (const float4*)(Wvg + (size_t)(l + 1) * 2500);
                for (int idx = tid - 256; idx < 625; idx += 256) {
                    dst[idx] = ws4[idx];
                    dst[idx + 625] = wg4[idx];
                    dst[idx + 1250] = wv4[idx];
                }
            }
        }
        __syncthreads();
    }

    // ---- epilogue ----
    if (k < 6) {
        int off = k + (k >= 4 ? 1 : 0);   // n4{0,1} n3{2,3} n5{5,6} in [50][8]
        float acc = 0.f;
        #pragma unroll 5
        for (int c = 0; c < 50; c++) acc += st[OF_VC + c * 8 + off] * __ldg(Woutg + c);
        g[28 + k] = acc;
    }
    __syncthreads();
    if (k == 0) {
        float o4x = g[28], o4y = g[29], o3x = g[30], o3y = g[31], o5x = g[32], o5y = g[33];
        float ox = g[17], oy = g[18];
        float* dst = outp + (size_t)(b * 514 + i + 1) * 3;
        dst[0] = o3x + o4x + o5x;
        dst[1] = o3y + o4y + o5y;
        dst[2] = ox * (o3y - o5y) - oy * (o3x - o5x);
    }
}

extern "C" void kernel_launch(void* const* d_in, const int* in_sizes, int n_in,
                              void* d_out, int out_size) {
    const float* y    = (const float*)d_in[0];
    const float* Wemb = (const float*)d_in[1];
    const float* Wr1  = (const float*)d_in[2];
    const float* br1  = (const float*)d_in[3];
    const float* Wr2  = (const float*)d_in[4];
    const float* Ws   = (const float*)d_in[5];
    const float* Wv   = (const float*)d_in[6];
    const float* Wg   = (const float*)d_in[7];
    const float* Wo   = (const float*)d_in[8];
    float* outp = (float*)d_out;

    cudaMemsetAsync(outp, 0, (size_t)out_size * sizeof(float));
    setup_kernel<<<1, 256>>>(Wemb, Wr1, br1, Wr2, Ws);
    cudaFuncSetAttribute(e3nn_kernel, cudaFuncAttributeMaxDynamicSharedMemorySize, SMEM_BYTES);
    e3nn_kernel<<<NBLK, NTHR, SMEM_BYTES>>>(y, Wemb, Wr1, br1, Wr2, Ws, Wv, Wg, Wo, outp);
}